// round 8
// baseline (speedup 1.0000x reference)
#include <cuda_runtime.h>
#include <math.h>

#define B_ 4
#define C_ 32
#define L_ 256
#define M_ 256
#define F_ 8
#define N_ 64
#define CL_ (L_ * M_)      // c-stride in x (elements)

typedef unsigned long long u64;

__device__ __forceinline__ u64 ffma2(u64 a, u64 b, u64 c) {
    u64 d;
    asm("fma.rn.f32x2 %0, %1, %2, %3;" : "=l"(d) : "l"(a), "l"(b), "l"(c));
    return d;
}
__device__ __forceinline__ void upk(u64 v, float& x, float& y) {
    asm("mov.b64 {%0, %1}, %2;" : "=f"(x), "=f"(y) : "l"(v));
}
// Flip sign of both f32 lanes (ALU pipe, mostly idle).
__device__ __forceinline__ u64 neg2(u64 v) {
    u64 d;
    asm("{\n\t"
        ".reg .b32 lo, hi;\n\t"
        "mov.b64 {lo, hi}, %1;\n\t"
        "xor.b32 lo, lo, 0x80000000;\n\t"
        "xor.b32 hi, hi, 0x80000000;\n\t"
        "mov.b64 %0, {lo, hi};\n\t"
        "}" : "=l"(d) : "l"(v));
    return d;
}

__global__ __launch_bounds__(256, 4) void sphere_conv_kernel(
    const float* __restrict__ xr, const float* __restrict__ xi,
    const float* __restrict__ wr, const float* __restrict__ wi,
    float* __restrict__ out)
{
    // two weight sets (one per l in the pair): {wr,wr,wi,wi} per (f,c)
    __shared__ float4 w4s[2][C_ * F_];           // 8 KB

    const int tid  = threadIdx.x;
    const int mp   = tid & 127;          // m-pair: owns m = 2*mp, 2*mp+1
    const int lsel = tid >> 7;           // 0/1: which l of the pair
    const int b    = blockIdx.x >> 7;    // 4 b's x 128 l-pairs
    const int l    = ((blockIdx.x & 127) << 1) + lsel;

    // ---- interpolated weights for this group's l ----
    const float t = (float)(l * (N_ - 1)) * (1.0f / (float)(L_ - 1));
    int lo = (int)t;
    if (lo > N_ - 2) lo = N_ - 2;
    const float frac = t - (float)lo;
    const float om   = 1.0f - frac;
    for (int i = mp; i < F_ * C_; i += 128) {
        const int f = i & (F_ - 1);
        const int c = i >> 3;
        const int wix = (f * C_ + c) * N_ + lo;      // w layout (F,C,N,1)
        const float wrv = wr[wix] * om + wr[wix + 1] * frac;
        const float wiv = wi[wix] * om + wi[wix + 1] * frac;
        w4s[lsel][c * F_ + f] = make_float4(wrv, wrv, wiv, wiv);
    }
    __syncthreads();

    const unsigned int sw =
        (unsigned int)__cvta_generic_to_shared(&w4s[lsel][0]);

    u64 pr[F_], pi[F_];
#pragma unroll
    for (int f = 0; f < F_; ++f) { pr[f] = 0ull; pi[f] = 0ull; }

    // x index: ((b*C + c)*L + l)*M + m ; whole CTA covers 2KB per (c, re/im)
    const int base = b * (C_ * CL_) + l * M_ + 2 * mp;
    const float* xrp = xr + base;
    const float* xip = xi + base;

    // rolling double-buffered c-PAIRS (proven in R3)
    u64 buf[2][2][2];                    // [dbuf][c-in-pair][xr,xi]
#pragma unroll
    for (int j = 0; j < 2; ++j) {
        buf[0][j][0] = *(const u64*)(xrp + j * CL_);
        buf[0][j][1] = *(const u64*)(xip + j * CL_);
    }
    unsigned int soff = sw;
#pragma unroll
    for (int cp = 0; cp < 16; ++cp) {
        const int cur = cp & 1, nxt = cur ^ 1;
        if (cp < 15) {
#pragma unroll
            for (int j = 0; j < 2; ++j) {
                const int c = (cp + 1) * 2 + j;
                buf[nxt][j][0] = *(const u64*)(xrp + c * CL_);
                buf[nxt][j][1] = *(const u64*)(xip + c * CL_);
            }
        }
#pragma unroll
        for (int j = 0; j < 2; ++j) {
            const u64 x_r = buf[cur][j][0];
            const u64 x_i = buf[cur][j][1];
            const u64 nxi = neg2(x_i);
#pragma unroll
            for (int f = 0; f < F_; ++f) {
                u64 wrr, wii;
                asm("ld.shared.v2.u64 {%0, %1}, [%2];"
                    : "=l"(wrr), "=l"(wii)
                    : "r"(soff + (unsigned)(f * 16)));
                pr[f] = ffma2(wrr, x_r, pr[f]);   // + wr*xr
                pr[f] = ffma2(wii, nxi, pr[f]);   // - wi*xi
                pi[f] = ffma2(wii, x_r, pi[f]);   // + wi*xr
                pi[f] = ffma2(wrr, x_i, pi[f]);   // + wr*xi
            }
            soff += F_ * 16;             // next c
        }
    }

    // ---- epilogue: scale = sqrt(1+l)/C, relu on real only ----
    const float s  = sqrtf(1.0f + (float)l) * (1.0f / (float)C_);
    float2* outp   = (float2*)out;
    const int ob   = (b * F_ * L_ + l) * M_ + 2 * mp;
#pragma unroll
    for (int f = 0; f < F_; ++f) {
        float r0, r1, i0, i1;
        upk(pr[f], r0, r1);
        upk(pi[f], i0, i1);
        const int idx = ob + f * (L_ * M_);
        outp[idx >> 1] = make_float2(fmaxf(r0 * s, 0.0f), fmaxf(r1 * s, 0.0f));
        outp[(idx + B_ * F_ * L_ * M_) >> 1] = make_float2(i0 * s, i1 * s);
    }
}

extern "C" void kernel_launch(void* const* d_in, const int* in_sizes, int n_in,
                              void* d_out, int out_size) {
    (void)in_sizes; (void)n_in; (void)out_size;
    sphere_conv_kernel<<<512, 256>>>(
        (const float*)d_in[0], (const float*)d_in[1],
        (const float*)d_in[2], (const float*)d_in[3],
        (float*)d_out);
}

// round 10
// speedup vs baseline: 1.6000x; 1.6000x over previous
#include <cuda_runtime.h>
#include <math.h>

#define B_ 4
#define C_ 32
#define L_ 256
#define M_ 256
#define F_ 8
#define N_ 64
#define CL_ (L_ * M_)          // c-stride in x (elements)
#define NSTG_ 8                // 8 stages x 4 c's, no ring reuse
#define CPS_ 4
#define STGB_ 8192             // bytes per stage: 4 c x (re+im) x 1KB

// dynamic smem layout
#define XS_BYTES   (NSTG_ * STGB_)          // 65536
#define W_OFF      XS_BYTES                 // 65536
#define W_BYTES    (C_ * F_ * 16)           // 4096
#define MB_OFF     (W_OFF + W_BYTES)        // 69632
#define SMEM_TOTAL (MB_OFF + NSTG_ * 8)     // 69696

typedef unsigned long long u64;

__device__ __forceinline__ u64 ffma2(u64 a, u64 b, u64 c) {
    u64 d;
    asm("fma.rn.f32x2 %0, %1, %2, %3;" : "=l"(d) : "l"(a), "l"(b), "l"(c));
    return d;
}
__device__ __forceinline__ void upk(u64 v, float& x, float& y) {
    asm("mov.b64 {%0, %1}, %2;" : "=f"(x), "=f"(y) : "l"(v));
}
__device__ __forceinline__ u64 neg2(u64 v) {
    u64 d;
    asm("{\n\t"
        ".reg .b32 lo, hi;\n\t"
        "mov.b64 {lo, hi}, %1;\n\t"
        "xor.b32 lo, lo, 0x80000000;\n\t"
        "xor.b32 hi, hi, 0x80000000;\n\t"
        "mov.b64 %0, {lo, hi};\n\t"
        "}" : "=l"(d) : "l"(v));
    return d;
}
// 1D TMA bulk copy: 1KB global -> shared, completion on mbarrier (tx bytes).
__device__ __forceinline__ void bulk1k(unsigned int sdst, const void* gsrc,
                                       unsigned int mbar) {
    asm volatile(
        "cp.async.bulk.shared::cta.global.mbarrier::complete_tx::bytes "
        "[%0], [%1], 1024, [%2];"
        :: "r"(sdst), "l"(gsrc), "r"(mbar) : "memory");
}
__device__ __forceinline__ void mbar_wait0(unsigned int mbar) {
    asm volatile(
        "{\n\t"
        ".reg .pred P1;\n\t"
        "WAIT_%=:\n\t"
        "mbarrier.try_wait.parity.acquire.cta.shared::cta.b64 P1, [%0], 0, 0x989680;\n\t"
        "@P1 bra.uni DONE_%=;\n\t"
        "bra.uni WAIT_%=;\n\t"
        "DONE_%=:\n\t"
        "}" :: "r"(mbar) : "memory");
}

__global__ __launch_bounds__(128) void sphere_conv_kernel(
    const float* __restrict__ xr, const float* __restrict__ xi,
    const float* __restrict__ wr, const float* __restrict__ wi,
    float* __restrict__ out)
{
    extern __shared__ char smem[];
    float4* w4s = (float4*)(smem + W_OFF);

    const unsigned int sx  = (unsigned int)__cvta_generic_to_shared(smem);
    const unsigned int swb = sx + W_OFF;
    const unsigned int smb = sx + MB_OFF;

    const int tid = threadIdx.x;
    const int bl  = blockIdx.x;          // b*L + l
    const int b   = bl >> 8;             // L_ == 256
    const int l   = bl & (L_ - 1);

    // ---- init one single-use mbarrier per stage ----
    if (tid == 0) {
#pragma unroll
        for (int sg = 0; sg < NSTG_; ++sg)
            asm volatile("mbarrier.init.shared.b64 [%0], 1;"
                         :: "r"(smb + sg * 8) : "memory");
    }

    // ---- interpolated weights into smem: {wr,wr,wi,wi} per (f,c) ----
    const float t = (float)(l * (N_ - 1)) * (1.0f / (float)(L_ - 1));
    int lo = (int)t;
    if (lo > N_ - 2) lo = N_ - 2;
    const float frac = t - (float)lo;
    const float om   = 1.0f - frac;
    for (int i = tid; i < F_ * C_; i += 128) {
        const int f = i & (F_ - 1);
        const int c = i >> 3;
        const int wix = (f * C_ + c) * N_ + lo;      // w layout (F,C,N,1)
        const float wrv = wr[wix] * om + wr[wix + 1] * frac;
        const float wiv = wi[wix] * om + wi[wix + 1] * frac;
        w4s[c * F_ + f] = make_float4(wrv, wrv, wiv, wiv);
    }
    __syncthreads();   // mbars visible + weights written before any wait/read

    // ---- issue ALL TMA loads upfront (64 x 1KB rows, 64KB per CTA) ----
    if (tid == 0) {
        const char* xrg = (const char*)(xr + (size_t)b * (C_ * CL_) + l * M_);
        const char* xig = (const char*)(xi + (size_t)b * (C_ * CL_) + l * M_);
#pragma unroll
        for (int sg = 0; sg < NSTG_; ++sg) {
            const unsigned int mb = smb + sg * 8;
            asm volatile("mbarrier.arrive.expect_tx.shared.b64 _, [%0], %1;"
                         :: "r"(mb), "r"((unsigned)STGB_) : "memory");
#pragma unroll
            for (int j = 0; j < CPS_; ++j) {
                const size_t coff = (size_t)(sg * CPS_ + j) * (CL_ * 4);
                const unsigned int sd = sx + sg * STGB_ + j * 2048;
                bulk1k(sd,        xrg + coff, mb);
                bulk1k(sd + 1024, xig + coff, mb);
            }
        }
    }

    u64 pr[F_], pi[F_];
#pragma unroll
    for (int f = 0; f < F_; ++f) { pr[f] = 0ull; pi[f] = 0ull; }

    const unsigned int sxr = sx + (unsigned)(tid * 8);
    unsigned int soff = swb;

#pragma unroll 1
    for (int sg = 0; sg < NSTG_; ++sg) {
        mbar_wait0(smb + sg * 8);        // stage resident; per-warp, no bar.sync
        const unsigned int st = sxr + (unsigned)(sg * STGB_);
#pragma unroll
        for (int j = 0; j < CPS_; ++j) {
            u64 x_r, x_i;
            asm("ld.shared.b64 %0, [%1];" : "=l"(x_r)
                : "r"(st + (unsigned)(j * 2048)));
            asm("ld.shared.b64 %0, [%1];" : "=l"(x_i)
                : "r"(st + (unsigned)(j * 2048 + 1024)));
            const u64 nxi = neg2(x_i);
#pragma unroll
            for (int f = 0; f < F_; ++f) {
                u64 wrr, wii;
                asm("ld.shared.v2.u64 {%0, %1}, [%2];"
                    : "=l"(wrr), "=l"(wii)
                    : "r"(soff + (unsigned)(f * 16)));
                pr[f] = ffma2(wrr, x_r, pr[f]);   // + wr*xr
                pr[f] = ffma2(wii, nxi, pr[f]);   // - wi*xi
                pi[f] = ffma2(wii, x_r, pi[f]);   // + wi*xr
                pi[f] = ffma2(wrr, x_i, pi[f]);   // + wr*xi
            }
            soff += F_ * 16;
        }
    }

    // ---- epilogue: scale = sqrt(1+l)/C, relu on real only ----
    const float s  = sqrtf(1.0f + (float)l) * (1.0f / (float)C_);
    float2* outp   = (float2*)out;
    const int ob   = (b * F_ * L_ + l) * M_ + 2 * tid;
#pragma unroll
    for (int f = 0; f < F_; ++f) {
        float r0, r1, i0, i1;
        upk(pr[f], r0, r1);
        upk(pi[f], i0, i1);
        const int idx = ob + f * (L_ * M_);
        outp[idx >> 1] = make_float2(fmaxf(r0 * s, 0.0f), fmaxf(r1 * s, 0.0f));
        outp[(idx + B_ * F_ * L_ * M_) >> 1] = make_float2(i0 * s, i1 * s);
    }
}

extern "C" void kernel_launch(void* const* d_in, const int* in_sizes, int n_in,
                              void* d_out, int out_size) {
    (void)in_sizes; (void)n_in; (void)out_size;
    cudaFuncSetAttribute(sphere_conv_kernel,
                         cudaFuncAttributeMaxDynamicSharedMemorySize, SMEM_TOTAL);
    sphere_conv_kernel<<<B_ * L_, 128, SMEM_TOTAL>>>(
        (const float*)d_in[0], (const float*)d_in[1],
        (const float*)d_in[2], (const float*)d_in[3],
        (float*)d_out);
}

// round 11
// speedup vs baseline: 1.8111x; 1.1319x over previous
#include <cuda_runtime.h>
#include <math.h>

#define B_ 4
#define C_ 32
#define L_ 256
#define M_ 256
#define F_ 8
#define N_ 64
#define CL_ (L_ * M_)      // c-stride in x (elements)

typedef unsigned long long u64;

__device__ __forceinline__ u64 ffma2(u64 a, u64 b, u64 c) {
    u64 d;
    asm("fma.rn.f32x2 %0, %1, %2, %3;" : "=l"(d) : "l"(a), "l"(b), "l"(c));
    return d;
}
__device__ __forceinline__ void upk(u64 v, float& x, float& y) {
    asm("mov.b64 {%0, %1}, %2;" : "=f"(x), "=f"(y) : "l"(v));
}
// Flip sign of both f32 lanes (ALU pipe, mostly idle).
__device__ __forceinline__ u64 neg2(u64 v) {
    u64 d;
    asm("{\n\t"
        ".reg .b32 lo, hi;\n\t"
        "mov.b64 {lo, hi}, %1;\n\t"
        "xor.b32 lo, lo, 0x80000000;\n\t"
        "xor.b32 hi, hi, 0x80000000;\n\t"
        "mov.b64 %0, {lo, hi};\n\t"
        "}" : "=l"(d) : "l"(v));
    return d;
}

// NOTE: (256, 2) -> up to 128 regs/thread. R8 used (256,4) which capped regs
// at 64 and silently destroyed the prefetch schedule. That was the regression.
__global__ __launch_bounds__(256, 2) void sphere_conv_kernel(
    const float* __restrict__ xr, const float* __restrict__ xi,
    const float* __restrict__ wr, const float* __restrict__ wi,
    float* __restrict__ out)
{
    // two weight sets (one per l in the pair): {wr,wr,wi,wi} per (f,c)
    __shared__ float4 w4s[2][C_ * F_];           // 8 KB

    const int tid  = threadIdx.x;
    const int mp   = tid & 127;          // m-pair: owns m = 2*mp, 2*mp+1
    const int lsel = tid >> 7;           // 0/1: which l of the pair
    const int b    = blockIdx.x >> 7;    // 4 b's x 128 l-pairs
    const int l    = ((blockIdx.x & 127) << 1) + lsel;

    // ---- interpolated weights for this group's l ----
    const float t = (float)(l * (N_ - 1)) * (1.0f / (float)(L_ - 1));
    int lo = (int)t;
    if (lo > N_ - 2) lo = N_ - 2;
    const float frac = t - (float)lo;
    const float om   = 1.0f - frac;
    for (int i = mp; i < F_ * C_; i += 128) {
        const int f = i & (F_ - 1);
        const int c = i >> 3;
        const int wix = (f * C_ + c) * N_ + lo;      // w layout (F,C,N,1)
        const float wrv = wr[wix] * om + wr[wix + 1] * frac;
        const float wiv = wi[wix] * om + wi[wix + 1] * frac;
        w4s[lsel][c * F_ + f] = make_float4(wrv, wrv, wiv, wiv);
    }
    __syncthreads();

    const unsigned int sw =
        (unsigned int)__cvta_generic_to_shared(&w4s[lsel][0]);

    u64 pr[F_], pi[F_];
#pragma unroll
    for (int f = 0; f < F_; ++f) { pr[f] = 0ull; pi[f] = 0ull; }

    // x index: ((b*C + c)*L + l)*M + m ; whole CTA covers 2KB per (c, re/im)
    const int base = b * (C_ * CL_) + l * M_ + 2 * mp;
    const float* xrp = xr + base;
    const float* xip = xi + base;

    // rolling double-buffered c-PAIRS (lookahead = 2..4 c's, ~16 MLP regs)
    u64 buf[2][2][2];                    // [dbuf][c-in-pair][xr,xi]
#pragma unroll
    for (int j = 0; j < 2; ++j) {
        buf[0][j][0] = *(const u64*)(xrp + j * CL_);
        buf[0][j][1] = *(const u64*)(xip + j * CL_);
    }
    unsigned int soff = sw;
#pragma unroll
    for (int cp = 0; cp < 16; ++cp) {
        const int cur = cp & 1, nxt = cur ^ 1;
        if (cp < 15) {
#pragma unroll
            for (int j = 0; j < 2; ++j) {
                const int c = (cp + 1) * 2 + j;
                buf[nxt][j][0] = *(const u64*)(xrp + c * CL_);
                buf[nxt][j][1] = *(const u64*)(xip + c * CL_);
            }
        }
#pragma unroll
        for (int j = 0; j < 2; ++j) {
            const u64 x_r = buf[cur][j][0];
            const u64 x_i = buf[cur][j][1];
            const u64 nxi = neg2(x_i);
#pragma unroll
            for (int f = 0; f < F_; ++f) {
                u64 wrr, wii;
                asm("ld.shared.v2.u64 {%0, %1}, [%2];"
                    : "=l"(wrr), "=l"(wii)
                    : "r"(soff + (unsigned)(f * 16)));
                pr[f] = ffma2(wrr, x_r, pr[f]);   // + wr*xr
                pr[f] = ffma2(wii, nxi, pr[f]);   // - wi*xi
                pi[f] = ffma2(wii, x_r, pi[f]);   // + wi*xr
                pi[f] = ffma2(wrr, x_i, pi[f]);   // + wr*xi
            }
            soff += F_ * 16;             // next c
        }
    }

    // ---- epilogue: scale = sqrt(1+l)/C, relu on real only ----
    const float s  = sqrtf(1.0f + (float)l) * (1.0f / (float)C_);
    float2* outp   = (float2*)out;
    const int ob   = (b * F_ * L_ + l) * M_ + 2 * mp;
#pragma unroll
    for (int f = 0; f < F_; ++f) {
        float r0, r1, i0, i1;
        upk(pr[f], r0, r1);
        upk(pi[f], i0, i1);
        const int idx = ob + f * (L_ * M_);
        outp[idx >> 1] = make_float2(fmaxf(r0 * s, 0.0f), fmaxf(r1 * s, 0.0f));
        outp[(idx + B_ * F_ * L_ * M_) >> 1] = make_float2(i0 * s, i1 * s);
    }
}

extern "C" void kernel_launch(void* const* d_in, const int* in_sizes, int n_in,
                              void* d_out, int out_size) {
    (void)in_sizes; (void)n_in; (void)out_size;
    sphere_conv_kernel<<<512, 256>>>(
        (const float*)d_in[0], (const float*)d_in[1],
        (const float*)d_in[2], (const float*)d_in[3],
        (float*)d_out);
}